// round 1
// baseline (speedup 1.0000x reference)
#include <cuda_runtime.h>

#define N_SPH 128
typedef unsigned long long u64;

// 14 packed (duplicated) consts per sphere = 28 floats.
// Layout per sphere (each value stored twice, adjacent):
//  [T00 T01 T02 -cx  T10 T11 T12 -cy  T20 T21 T22 -cz  b  pad]
//  where b = 32 * log2(e) * radius.
__device__ __align__(16) float g_consts[N_SPH * 28];

__global__ void precompute_spheres(const float* __restrict__ centers,
                                   const float* __restrict__ radii,
                                   const float* __restrict__ tfs) {
    int i = blockIdx.x * blockDim.x + threadIdx.x;
    if (i >= N_SPH) return;
    float cs[14];
    #pragma unroll
    for (int r = 0; r < 3; ++r) {
        #pragma unroll
        for (int c = 0; c < 3; ++c)
            cs[r * 4 + c] = tfs[i * 9 + r * 3 + c] + ((r == c) ? 1.0f : 0.0f);
        cs[r * 4 + 3] = -centers[i * 3 + r];
    }
    cs[12] = 46.16624130844683f * radii[i];  // 32 * log2(e) * r
    cs[13] = 0.0f;
    #pragma unroll
    for (int j = 0; j < 14; ++j) {
        g_consts[i * 28 + 2 * j]     = cs[j];
        g_consts[i * 28 + 2 * j + 1] = cs[j];
    }
}

// ---- packed f32x2 helpers (sm_100+) ----
__device__ __forceinline__ u64 pk2(float lo, float hi) {
    u64 r;
    asm("mov.b64 %0, {%1, %2};" : "=l"(r) : "f"(lo), "f"(hi));
    return r;
}
__device__ __forceinline__ float2 up2(u64 v) {
    float2 f;
    asm("mov.b64 {%0, %1}, %2;" : "=f"(f.x), "=f"(f.y) : "l"(v));
    return f;
}
__device__ __forceinline__ u64 f2fma(u64 a, u64 b, u64 c) {
    u64 d;
    asm("fma.rn.f32x2 %0, %1, %2, %3;" : "=l"(d) : "l"(a), "l"(b), "l"(c));
    return d;
}
__device__ __forceinline__ u64 f2mul(u64 a, u64 b) {
    u64 d;
    asm("mul.rn.f32x2 %0, %1, %2;" : "=l"(d) : "l"(a), "l"(b));
    return d;
}
__device__ __forceinline__ float sqrt_ap(float x) {
    float r;
    asm("sqrt.approx.f32 %0, %1;" : "=f"(r) : "f"(x));
    return r;
}
__device__ __forceinline__ float ex2_ap(float x) {
    float r;
    asm("ex2.approx.f32 %0, %1;" : "=f"(r) : "f"(x));
    return r;
}
__device__ __forceinline__ float lg2_ap(float x) {
    float r;
    asm("lg2.approx.f32 %0, %1;" : "=f"(r) : "f"(x));
    return r;
}

__global__ void __launch_bounds__(256) smoothed_spheres(
    const float* __restrict__ p, float* __restrict__ out, int npts) {
    __shared__ u64 shc[N_SPH * 14];
    {
        const u64* gc = reinterpret_cast<const u64*>(g_consts);
        for (int i = threadIdx.x; i < N_SPH * 14; i += 256) shc[i] = gc[i];
    }
    __syncthreads();

    int base = (blockIdx.x * 256 + threadIdx.x) * 4;
    if (base >= npts) return;

    // 4 points = 12 floats = 3 float4 loads (coalesced, 16B aligned: 48B/thread)
    const float4* p4 = reinterpret_cast<const float4*>(p);
    int f4 = (base >> 2) * 3;
    float4 va = p4[f4], vb = p4[f4 + 1], vc = p4[f4 + 2];

    // pair0 = points (0,1), pair1 = points (2,3)
    u64 X0 = pk2(va.x, va.w), Y0 = pk2(va.y, vb.x), Z0 = pk2(va.z, vb.y);
    u64 X1 = pk2(vb.z, vc.y), Y1 = pk2(vb.w, vc.z), Z1 = pk2(vc.x, vc.w);

    const float Acoef = -46.16624130844683f;  // -32 * log2(e)
    u64 A2 = pk2(Acoef, Acoef);

    float s0 = 0.f, s1 = 0.f, s2 = 0.f, s3 = 0.f;

    for (int sp = 0; sp < N_SPH; ++sp) {
        const u64* C = shc + sp * 14;
        u64 t00 = C[0], t01 = C[1],  t02 = C[2],  ncx = C[3];
        u64 t10 = C[4], t11 = C[5],  t12 = C[6],  ncy = C[7];
        u64 t20 = C[8], t21 = C[9],  t22 = C[10], ncz = C[11];
        u64 bb  = C[12];

        // q = T*p - c for both packed pairs (9 f32x2 FMAs each)
        u64 qx0 = f2fma(t00, X0, f2fma(t01, Y0, f2fma(t02, Z0, ncx)));
        u64 qy0 = f2fma(t10, X0, f2fma(t11, Y0, f2fma(t12, Z0, ncy)));
        u64 qz0 = f2fma(t20, X0, f2fma(t21, Y0, f2fma(t22, Z0, ncz)));
        u64 qx1 = f2fma(t00, X1, f2fma(t01, Y1, f2fma(t02, Z1, ncx)));
        u64 qy1 = f2fma(t10, X1, f2fma(t11, Y1, f2fma(t12, Z1, ncy)));
        u64 qz1 = f2fma(t20, X1, f2fma(t21, Y1, f2fma(t22, Z1, ncz)));

        // d2 = qx^2 + qy^2 + qz^2  (>= 0 by construction)
        u64 d20 = f2fma(qx0, qx0, f2fma(qy0, qy0, f2mul(qz0, qz0)));
        u64 d21 = f2fma(qx1, qx1, f2fma(qy1, qy1, f2mul(qz1, qz1)));

        float2 da = up2(d20), db = up2(d21);
        float r0 = sqrt_ap(da.x), r1 = sqrt_ap(da.y);
        float r2 = sqrt_ap(db.x), r3 = sqrt_ap(db.y);

        // exp(-32*(d - r)) = 2^(A*d + b), packed FMA for the arg
        u64 g0 = f2fma(A2, pk2(r0, r1), bb);
        u64 g1 = f2fma(A2, pk2(r2, r3), bb);
        float2 ga = up2(g0), gb = up2(g1);

        s0 += ex2_ap(ga.x);
        s1 += ex2_ap(ga.y);
        s2 += ex2_ap(gb.x);
        s3 += ex2_ap(gb.y);
    }

    // out = -ln(max(s, 1e-6)) / 32 = lg2(s) * (-ln2/32)
    const float NEG_LN2_32 = -0.021660849392498290f;
    float4 o;
    o.x = lg2_ap(fmaxf(s0, 1e-6f)) * NEG_LN2_32;
    o.y = lg2_ap(fmaxf(s1, 1e-6f)) * NEG_LN2_32;
    o.z = lg2_ap(fmaxf(s2, 1e-6f)) * NEG_LN2_32;
    o.w = lg2_ap(fmaxf(s3, 1e-6f)) * NEG_LN2_32;
    reinterpret_cast<float4*>(out)[base >> 2] = o;
}

extern "C" void kernel_launch(void* const* d_in, const int* in_sizes, int n_in,
                              void* d_out, int out_size) {
    const float* p       = (const float*)d_in[0];
    const float* centers = (const float*)d_in[1];
    const float* radii   = (const float*)d_in[2];
    const float* tfs     = (const float*)d_in[3];
    float* out = (float*)d_out;

    int npts = in_sizes[0] / 3;

    precompute_spheres<<<1, N_SPH>>>(centers, radii, tfs);

    int threads = 256;
    int pts_per_block = threads * 4;
    int blocks = (npts + pts_per_block - 1) / pts_per_block;
    smoothed_spheres<<<blocks, threads>>>(p, out, npts);
}

// round 2
// speedup vs baseline: 2.1036x; 2.1036x over previous
#include <cuda_runtime.h>
#include <math.h>

#define N_SPH 128
#define MAX_PTS (1 << 20)
typedef unsigned long long u64;

// Per-sphere packed consts: 14 u64 (each f32 duplicated into both lanes):
// [T00 T01 | T02 -cx | T10 T11 | T12 -cy | T20 T21 | T22 -cz | b pad]
// b = 32*log2(e)*radius
__device__ __align__(16) float g_consts[N_SPH * 28];
__device__ float g_R2;       // squared norm threshold for the fast path
__device__ int   g_count;    // number of compacted near points
__device__ float4 g_comp[MAX_PTS];  // compacted near points: (x,y,z, idx-as-float)

// -ln(1e-6)/32 : exact output when s clamps
#define FASTVAL 0.4317347049363836f

__global__ void precompute_spheres(const float* __restrict__ centers,
                                   const float* __restrict__ radii,
                                   const float* __restrict__ tfs) {
    __shared__ float sthr[N_SPH];
    int i = threadIdx.x;

    float T[3][3];
    #pragma unroll
    for (int r = 0; r < 3; ++r)
        #pragma unroll
        for (int c = 0; c < 3; ++c)
            T[r][c] = tfs[i * 9 + r * 3 + c] + ((r == c) ? 1.0f : 0.0f);

    float cs[14];
    #pragma unroll
    for (int r = 0; r < 3; ++r) {
        cs[r * 4 + 0] = T[r][0];
        cs[r * 4 + 1] = T[r][1];
        cs[r * 4 + 2] = T[r][2];
        cs[r * 4 + 3] = -centers[i * 3 + r];
    }
    cs[12] = 46.16624130844683f * radii[i];  // 32*log2(e)*r
    cs[13] = 0.0f;
    #pragma unroll
    for (int j = 0; j < 14; ++j) {
        g_consts[i * 28 + 2 * j]     = cs[j];
        g_consts[i * 28 + 2 * j + 1] = cs[j];
    }

    // sigma_min(T) = sqrt(lambda_min(T^T T)), analytic 3x3 symmetric eigen, fp64
    double M00 = 0, M11 = 0, M22 = 0, M01 = 0, M02 = 0, M12 = 0;
    #pragma unroll
    for (int k = 0; k < 3; ++k) {
        double t0 = T[k][0], t1 = T[k][1], t2 = T[k][2];
        M00 += t0 * t0; M11 += t1 * t1; M22 += t2 * t2;
        M01 += t0 * t1; M02 += t0 * t2; M12 += t1 * t2;
    }
    double q = (M00 + M11 + M22) / 3.0;
    double p1 = M01 * M01 + M02 * M02 + M12 * M12;
    double a0 = M00 - q, a1 = M11 - q, a2 = M22 - q;
    double p2 = a0 * a0 + a1 * a1 + a2 * a2 + 2.0 * p1;
    double lmin;
    if (p2 < 1e-24) {
        lmin = q;
    } else {
        double pp = sqrt(p2 / 6.0);
        double inv = 1.0 / pp;
        double b00 = a0 * inv, b11 = a1 * inv, b22 = a2 * inv;
        double b01 = M01 * inv, b02 = M02 * inv, b12 = M12 * inv;
        double detB = b00 * (b11 * b22 - b12 * b12)
                    - b01 * (b01 * b22 - b12 * b02)
                    + b02 * (b01 * b12 - b11 * b02);
        double rr = detB * 0.5;
        rr = fmin(1.0, fmax(-1.0, rr));
        double phi = acos(rr) / 3.0;
        lmin = q + 2.0 * pp * cos(phi + 2.0943951023931953);  // +2pi/3 -> smallest
    }
    double sig = sqrt(fmax(lmin, 0.0)) * 0.999;  // safety shrink
    double cx = centers[i * 3], cy = centers[i * 3 + 1], cz = centers[i * 3 + 2];
    double cn = sqrt(cx * cx + cy * cy + cz * cz);
    double num = 0.60 + cn + (double)radii[i];   // 0.60 > 0.5834 required bound
    double thr2;
    if (sig > 1e-9) {
        double thr = num / sig;
        thr2 = thr * thr * 1.0004;               // safety inflate
    } else {
        thr2 = 1e30;                             // no fast path (still correct)
    }
    sthr[i] = (float)fmin(thr2, 1e30);
    __syncthreads();
    for (int s = 64; s; s >>= 1) {
        if (i < s) sthr[i] = fmaxf(sthr[i], sthr[i + s]);
        __syncthreads();
    }
    if (i == 0) { g_R2 = sthr[0]; g_count = 0; }
}

__global__ void __launch_bounds__(256) classify_compact(
    const float* __restrict__ p, float* __restrict__ out, int npts) {
    int t = blockIdx.x * 256 + threadIdx.x;
    int base = t * 4;
    float R2 = g_R2;

    float x[4], y[4], z[4];
    bool near[4] = {false, false, false, false};
    int cnt = 0;
    if (base < npts) {
        const float4* p4 = reinterpret_cast<const float4*>(p);
        int f = t * 3;
        float4 va = p4[f], vb = p4[f + 1], vc = p4[f + 2];
        x[0] = va.x; y[0] = va.y; z[0] = va.z;
        x[1] = va.w; y[1] = vb.x; z[1] = vb.y;
        x[2] = vb.z; y[2] = vb.w; z[2] = vc.x;
        x[3] = vc.y; y[3] = vc.z; z[3] = vc.w;
        #pragma unroll
        for (int k = 0; k < 4; ++k) {
            float n2 = fmaf(x[k], x[k], fmaf(y[k], y[k], z[k] * z[k]));
            near[k] = n2 < R2;
            if (!near[k]) out[base + k] = FASTVAL;
            cnt += near[k] ? 1 : 0;
        }
    }

    // warp-aggregated compaction
    unsigned mask = 0xffffffffu;
    int lane = threadIdx.x & 31;
    int incl = cnt;
    #pragma unroll
    for (int d = 1; d < 32; d <<= 1) {
        int v = __shfl_up_sync(mask, incl, d);
        if (lane >= d) incl += v;
    }
    int total = __shfl_sync(mask, incl, 31);
    int wbase = 0;
    if (lane == 0 && total > 0) wbase = atomicAdd(&g_count, total);
    wbase = __shfl_sync(mask, wbase, 0);
    int off = wbase + incl - cnt;
    #pragma unroll
    for (int k = 0; k < 4; ++k) {
        if (near[k]) {
            g_comp[off] = make_float4(x[k], y[k], z[k], __int_as_float(base + k));
            off++;
        }
    }
}

// ---- packed f32x2 helpers (sm_100+) ----
__device__ __forceinline__ u64 pk2(float lo, float hi) {
    u64 r;
    asm("mov.b64 %0, {%1, %2};" : "=l"(r) : "f"(lo), "f"(hi));
    return r;
}
__device__ __forceinline__ float2 up2(u64 v) {
    float2 f;
    asm("mov.b64 {%0, %1}, %2;" : "=f"(f.x), "=f"(f.y) : "l"(v));
    return f;
}
__device__ __forceinline__ u64 f2fma(u64 a, u64 b, u64 c) {
    u64 d;
    asm("fma.rn.f32x2 %0, %1, %2, %3;" : "=l"(d) : "l"(a), "l"(b), "l"(c));
    return d;
}
__device__ __forceinline__ u64 f2mul(u64 a, u64 b) {
    u64 d;
    asm("mul.rn.f32x2 %0, %1, %2;" : "=l"(d) : "l"(a), "l"(b));
    return d;
}
__device__ __forceinline__ float sqrt_ap(float x) {
    float r;
    asm("sqrt.approx.f32 %0, %1;" : "=f"(r) : "f"(x));
    return r;
}
__device__ __forceinline__ float ex2_ap(float x) {
    float r;
    asm("ex2.approx.f32 %0, %1;" : "=f"(r) : "f"(x));
    return r;
}
__device__ __forceinline__ float lg2_ap(float x) {
    float r;
    asm("lg2.approx.f32 %0, %1;" : "=f"(r) : "f"(x));
    return r;
}

__global__ void __launch_bounds__(256) smoothed_main(float* __restrict__ out) {
    __shared__ ulonglong2 shc[N_SPH * 7];
    {
        const ulonglong2* gc = reinterpret_cast<const ulonglong2*>(g_consts);
        for (int i = threadIdx.x; i < N_SPH * 7; i += 256) shc[i] = gc[i];
    }
    __syncthreads();

    int count = g_count;
    int pairs = (count + 1) >> 1;
    int stride = gridDim.x * blockDim.x;

    for (int j = blockIdx.x * blockDim.x + threadIdx.x; j < pairs; j += stride) {
        int ia = 2 * j;
        int ib = 2 * j + 1;
        bool hasB = ib < count;
        float4 A = g_comp[ia];
        float4 B = g_comp[hasB ? ib : ia];

        u64 X = pk2(A.x, B.x), Y = pk2(A.y, B.y), Z = pk2(A.z, B.z);
        float s0 = 0.f, s1 = 0.f;

        #pragma unroll 2
        for (int sp = 0; sp < N_SPH; ++sp) {
            const ulonglong2* C = shc + sp * 7;
            ulonglong2 c0 = C[0], c1 = C[1], c2 = C[2], c3 = C[3];
            ulonglong2 c4 = C[4], c5 = C[5], c6 = C[6];

            u64 qx = f2fma(c0.x, X, f2fma(c0.y, Y, f2fma(c1.x, Z, c1.y)));
            u64 qy = f2fma(c2.x, X, f2fma(c2.y, Y, f2fma(c3.x, Z, c3.y)));
            u64 qz = f2fma(c4.x, X, f2fma(c4.y, Y, f2fma(c5.x, Z, c5.y)));
            u64 d2 = f2fma(qx, qx, f2fma(qy, qy, f2mul(qz, qz)));

            float2 d = up2(d2);
            float2 bs = up2(c6.x);
            float r0 = sqrt_ap(d.x), r1 = sqrt_ap(d.y);
            // exp(-32(||q||-r)) = 2^(-32*log2e*||q|| + b), imm-multiplier FFMA
            s0 += ex2_ap(fmaf(r0, -46.16624130844683f, bs.x));
            s1 += ex2_ap(fmaf(r1, -46.16624130844683f, bs.y));
        }

        const float NEG_LN2_32 = -0.021660849392498290f;
        out[__float_as_int(A.w)] = lg2_ap(fmaxf(s0, 1e-6f)) * NEG_LN2_32;
        if (hasB)
            out[__float_as_int(B.w)] = lg2_ap(fmaxf(s1, 1e-6f)) * NEG_LN2_32;
    }
}

extern "C" void kernel_launch(void* const* d_in, const int* in_sizes, int n_in,
                              void* d_out, int out_size) {
    const float* p       = (const float*)d_in[0];
    const float* centers = (const float*)d_in[1];
    const float* radii   = (const float*)d_in[2];
    const float* tfs     = (const float*)d_in[3];
    float* out = (float*)d_out;

    int npts = in_sizes[0] / 3;

    precompute_spheres<<<1, N_SPH>>>(centers, radii, tfs);

    int cblocks = (npts + 1023) / 1024;  // 4 points per thread, 256 threads
    classify_compact<<<cblocks, 256>>>(p, out, npts);

    smoothed_main<<<1184, 256>>>(out);
}

// round 3
// speedup vs baseline: 2.4417x; 1.1608x over previous
#include <cuda_runtime.h>
#include <math.h>

#define N_SPH 128
typedef unsigned long long u64;

// -ln(1e-6)/32 : exact output when s clamps at 1e-6
#define FASTVAL 0.4317347049363836f

// ---- packed f32x2 helpers (sm_100+) ----
__device__ __forceinline__ u64 pk2(float lo, float hi) {
    u64 r;
    asm("mov.b64 %0, {%1, %2};" : "=l"(r) : "f"(lo), "f"(hi));
    return r;
}
__device__ __forceinline__ float2 up2(u64 v) {
    float2 f;
    asm("mov.b64 {%0, %1}, %2;" : "=f"(f.x), "=f"(f.y) : "l"(v));
    return f;
}
__device__ __forceinline__ u64 f2fma(u64 a, u64 b, u64 c) {
    u64 d;
    asm("fma.rn.f32x2 %0, %1, %2, %3;" : "=l"(d) : "l"(a), "l"(b), "l"(c));
    return d;
}
__device__ __forceinline__ u64 f2mul(u64 a, u64 b) {
    u64 d;
    asm("mul.rn.f32x2 %0, %1, %2;" : "=l"(d) : "l"(a), "l"(b));
    return d;
}
__device__ __forceinline__ float sqrt_ap(float x) {
    float r;
    asm("sqrt.approx.f32 %0, %1;" : "=f"(r) : "f"(x));
    return r;
}
__device__ __forceinline__ float ex2_ap(float x) {
    float r;
    asm("ex2.approx.f32 %0, %1;" : "=f"(r) : "f"(x));
    return r;
}
__device__ __forceinline__ float lg2_ap(float x) {
    float r;
    asm("lg2.approx.f32 %0, %1;" : "=f"(r) : "f"(x));
    return r;
}

// One fused kernel: per-block sphere setup (redundant), classify 1024 points,
// compact near points into shared, run the packed f32x2 loop on the survivors.
__global__ void __launch_bounds__(256) smoothed_fused(
    const float* __restrict__ p,
    const float* __restrict__ centers,
    const float* __restrict__ radii,
    const float* __restrict__ tfs,
    float* __restrict__ out, int npts) {

    // consts: per sphere 14 u64 (each f32 duplicated) ->
    // [T00 T01 | T02 -cx | T10 T11 | T12 -cy | T20 T21 | T22 -cz | b pad]
    __shared__ __align__(16) u64   shc[N_SPH * 14];
    __shared__ float4 sbuf[1024];     // worst-case: every point is near
    __shared__ int    s_thr2_bits;    // threshold^2 as ordered int (all positive)
    __shared__ int    s_count;

    const int tid = threadIdx.x;
    if (tid == 0) { s_thr2_bits = 0; s_count = 0; }

    // ---- prefetch this thread's 4 points (hide DRAM under setup phase) ----
    int t = blockIdx.x * 256 + tid;
    int base = t * 4;
    float4 va, vb, vc;
    bool inb = base < npts;
    if (inb) {
        const float4* p4 = reinterpret_cast<const float4*>(p);
        int f = t * 3;
        va = p4[f]; vb = p4[f + 1]; vc = p4[f + 2];
    }
    __syncthreads();  // s_thr2_bits / s_count initialized

    // ---- phase A: threads 0..127 build sphere consts + radial threshold ----
    if (tid < N_SPH) {
        int i = tid;
        float T[3][3];
        #pragma unroll
        for (int r = 0; r < 3; ++r)
            #pragma unroll
            for (int c = 0; c < 3; ++c)
                T[r][c] = tfs[i * 9 + r * 3 + c] + ((r == c) ? 1.0f : 0.0f);
        float cx = centers[i * 3], cy = centers[i * 3 + 1], cz = centers[i * 3 + 2];
        float rad = radii[i];

        float* shf = reinterpret_cast<float*>(shc) + i * 28;
        #pragma unroll
        for (int r = 0; r < 3; ++r) {
            float cs3[4] = {T[r][0], T[r][1], T[r][2],
                            (r == 0 ? -cx : (r == 1 ? -cy : -cz))};
            #pragma unroll
            for (int c = 0; c < 4; ++c) {
                shf[(r * 4 + c) * 2]     = cs3[c];
                shf[(r * 4 + c) * 2 + 1] = cs3[c];
            }
        }
        float b = 46.16624130844683f * rad;  // 32*log2(e)*r
        shf[24] = b; shf[25] = b; shf[26] = 0.f; shf[27] = 0.f;

        // sigma_min lower bound: lambda_min(T^T T) >= q - 2*sqrt(p2/6)
        float M00 = 0, M11 = 0, M22 = 0, M01 = 0, M02 = 0, M12 = 0;
        #pragma unroll
        for (int k = 0; k < 3; ++k) {
            float t0 = T[k][0], t1 = T[k][1], t2 = T[k][2];
            M00 = fmaf(t0, t0, M00); M11 = fmaf(t1, t1, M11); M22 = fmaf(t2, t2, M22);
            M01 = fmaf(t0, t1, M01); M02 = fmaf(t0, t2, M02); M12 = fmaf(t1, t2, M12);
        }
        float q  = (M00 + M11 + M22) * (1.0f / 3.0f);
        float a0 = M00 - q, a1 = M11 - q, a2 = M22 - q;
        float p2 = a0 * a0 + a1 * a1 + a2 * a2
                 + 2.0f * (M01 * M01 + M02 * M02 + M12 * M12);
        // safety inflate the subtraction term against fp32 rounding
        float lmin = q - 2.001f * sqrtf(fmaxf(p2, 0.0f) * (1.0f / 6.0f)) - 1e-6f;
        float sig  = sqrtf(fmaxf(lmin, 0.0f)) * 0.999f;
        float cn   = sqrtf(cx * cx + cy * cy + cz * cz) * 1.0001f + 1e-7f;
        float num  = 0.601f + cn + rad;   // 0.601 > 0.5834 = (ln128+ln1e6)/32
        float thr2;
        if (sig > 1e-6f) {
            float thr = num / sig;
            thr2 = thr * thr * 1.002f;
        } else {
            thr2 = 1e30f;  // no culling; everything takes the slow (correct) path
        }
        atomicMax(&s_thr2_bits, __float_as_int(thr2));
    }
    __syncthreads();
    float R2 = __int_as_float(s_thr2_bits);

    // ---- phase B: classify 4 points, compact near ones into shared ----
    float x[4], y[4], z[4];
    bool nearf[4] = {false, false, false, false};
    int cnt = 0;
    if (inb) {
        x[0] = va.x; y[0] = va.y; z[0] = va.z;
        x[1] = va.w; y[1] = vb.x; z[1] = vb.y;
        x[2] = vb.z; y[2] = vb.w; z[2] = vc.x;
        x[3] = vc.y; y[3] = vc.z; z[3] = vc.w;
        #pragma unroll
        for (int k = 0; k < 4; ++k) {
            float n2 = fmaf(x[k], x[k], fmaf(y[k], y[k], z[k] * z[k]));
            nearf[k] = n2 < R2;
            if (!nearf[k]) out[base + k] = FASTVAL;
            cnt += nearf[k] ? 1 : 0;
        }
    }
    // warp-aggregated shared compaction
    unsigned mask = 0xffffffffu;
    int lane = tid & 31;
    int incl = cnt;
    #pragma unroll
    for (int d = 1; d < 32; d <<= 1) {
        int v = __shfl_up_sync(mask, incl, d);
        if (lane >= d) incl += v;
    }
    int total = __shfl_sync(mask, incl, 31);
    int wbase = 0;
    if (lane == 0 && total > 0) wbase = atomicAdd(&s_count, total);
    wbase = __shfl_sync(mask, wbase, 0);
    int off = wbase + incl - cnt;
    #pragma unroll
    for (int k = 0; k < 4; ++k) {
        if (nearf[k]) {
            sbuf[off] = make_float4(x[k], y[k], z[k], __int_as_float(base + k));
            off++;
        }
    }
    __syncthreads();

    // ---- phase C: packed f32x2 loop over compacted points (2 per thread) ----
    int count = s_count;
    int pairs = (count + 1) >> 1;

    for (int j = tid; j < pairs; j += 256) {
        int ia = 2 * j, ib = 2 * j + 1;
        bool hasB = ib < count;
        float4 A = sbuf[ia];
        float4 B = sbuf[hasB ? ib : ia];

        u64 X = pk2(A.x, B.x), Y = pk2(A.y, B.y), Z = pk2(A.z, B.z);
        float s0 = 0.f, s1 = 0.f;

        #pragma unroll 2
        for (int sp = 0; sp < N_SPH; ++sp) {
            const ulonglong2* C = reinterpret_cast<const ulonglong2*>(shc + sp * 14);
            ulonglong2 c0 = C[0], c1 = C[1], c2 = C[2], c3 = C[3];
            ulonglong2 c4 = C[4], c5 = C[5], c6 = C[6];

            u64 qx = f2fma(c0.x, X, f2fma(c0.y, Y, f2fma(c1.x, Z, c1.y)));
            u64 qy = f2fma(c2.x, X, f2fma(c2.y, Y, f2fma(c3.x, Z, c3.y)));
            u64 qz = f2fma(c4.x, X, f2fma(c4.y, Y, f2fma(c5.x, Z, c5.y)));
            u64 d2 = f2fma(qx, qx, f2fma(qy, qy, f2mul(qz, qz)));

            float2 d  = up2(d2);
            float2 bs = up2(c6.x);
            float r0 = sqrt_ap(d.x), r1 = sqrt_ap(d.y);
            // exp(-32(||q||-r)) = 2^(-32*log2e*||q|| + b)
            s0 += ex2_ap(fmaf(r0, -46.16624130844683f, bs.x));
            s1 += ex2_ap(fmaf(r1, -46.16624130844683f, bs.y));
        }

        const float NEG_LN2_32 = -0.021660849392498290f;
        out[__float_as_int(A.w)] = lg2_ap(fmaxf(s0, 1e-6f)) * NEG_LN2_32;
        if (hasB)
            out[__float_as_int(B.w)] = lg2_ap(fmaxf(s1, 1e-6f)) * NEG_LN2_32;
    }
}

extern "C" void kernel_launch(void* const* d_in, const int* in_sizes, int n_in,
                              void* d_out, int out_size) {
    const float* p       = (const float*)d_in[0];
    const float* centers = (const float*)d_in[1];
    const float* radii   = (const float*)d_in[2];
    const float* tfs     = (const float*)d_in[3];
    float* out = (float*)d_out;

    int npts = in_sizes[0] / 3;
    int blocks = (npts + 1023) / 1024;  // 256 threads x 4 points
    smoothed_fused<<<blocks, 256>>>(p, centers, radii, tfs, out, npts);
}